// round 9
// baseline (speedup 1.0000x reference)
#include <cuda_runtime.h>
#include <cuda_bf16.h>
#include <cstdint>

// Embedding gather: out[token, :] = W[:, ids[token]], W row-major [D_MODEL, VOCAB].
// R9: TILE_C=128 -> 16 independent LDG.32 per thread per chunk (2KB/warp in
// flight; iteration period >= DRAM latency so the STS wait vanishes), half the
// blocks -> half the filter traffic and barrier count. Single kernel.

#define VOCAB     50257
#define D_MODEL   1024
#define N_TOK     (4 * 4096)

#define TILE_C    128
#define TILE_BITS 7
#define N_TILES   ((VOCAB + TILE_C - 1) / TILE_C)   // 393
#define TILE_D    32
#define N_CHUNK   (D_MODEL / TILE_D)                // 32
#define PAD       (TILE_C + 1)                      // 129 (odd): conflict-free
#define STAGE_ELEMS (TILE_D * PAD)                  // 4128 floats
#define CAP       2048

__global__ __launch_bounds__(256, 4)
void gather_tile_kernel(const int* __restrict__ ids,
                        const float* __restrict__ W,
                        float* __restrict__ out) {
    const int tile = blockIdx.x;

    __shared__ float buf[2][STAGE_ELEMS];
    __shared__ int   s_list[CAP];
    __shared__ int   s_cnt;

    const int tid  = threadIdx.x;
    const int lane = tid & 31;
    const int wid  = tid >> 5;                 // 8 warps
    const int c0   = tile * TILE_C;

    // Load mapping: lc = column 0..127, lr = row-phase 0..1.
    // 16 passes of 2 rows cover the 32-row chunk; each warp's lanes are
    // contiguous columns -> every LDG/STS is a 128B contiguous op.
    const int lc = tid & (TILE_C - 1);
    const int lr = tid >> TILE_BITS;
    // Clamp OOB columns of last tile (never distributed: no id >= VOCAB).
    const int gcol = min(c0 + lc, VOCAB - 1);
    const float* __restrict__ col_base = W + gcol;

    if (tid == 0) s_cnt = 0;

    float rcur[16], rnext[16];

    // Prologue: issue chunk-0 DRAM loads first; the id-filter runs in their
    // shadow.
    #pragma unroll
    for (int p = 0; p < 16; p++)
        rcur[p] = __ldg(col_base + (long)(p * 2 + lr) * VOCAB);

    __syncthreads();   // s_cnt = 0 visible

    // Filter: find tokens whose id falls in this tile. Order irrelevant.
    const int4* __restrict__ ids4 = (const int4*)ids;
    for (int i = tid; i < N_TOK / 4; i += 256) {
        const int4 v = ids4[i];
        const int base_tok = i * 4;
        #pragma unroll
        for (int k = 0; k < 4; k++) {
            const int id = (&v.x)[k];
            if ((id >> TILE_BITS) == tile) {
                const int pos = atomicAdd(&s_cnt, 1);
                if (pos < CAP)
                    s_list[pos] = ((id & (TILE_C - 1)) << 16) | (base_tok + k);
            }
        }
    }
    __syncthreads();

    const int cnt = s_cnt;
    if (cnt == 0) return;                      // uniform: whole block exits
    const bool overflow = (cnt > CAP);
    const int n = overflow ? 0 : cnt;          // fast-path count

    for (int c = 0; c < N_CHUNK; c++) {
        // Issue chunk c+1 loads early (consumed next iteration).
        if (c + 1 < N_CHUNK) {
            #pragma unroll
            for (int p = 0; p < 16; p++)
                rnext[p] = __ldg(col_base + (long)((c + 1) * TILE_D + p * 2 + lr) * VOCAB);
        }

        // Stage chunk c to smem. Safe: buf[c&1] last distributed in iter c-2;
        // every warp passed iter c-1's barrier before this STS.
        float* sstage = &buf[c & 1][0];
        #pragma unroll
        for (int p = 0; p < 16; p++)
            sstage[(p * 2 + lr) * PAD + lc] = rcur[p];
        __syncthreads();

        // Distribute chunk c: row = lane -> one coalesced 128B store/token.
        const int d0 = c * TILE_D;
        for (int s = wid; s < n; s += 8) {
            const int pk    = s_list[s];
            const int col   = pk >> 16;
            const int token = pk & 0xFFFF;
            out[(long)token * D_MODEL + d0 + lane] = sstage[lane * PAD + col];
        }
        if (overflow) {
            // Correct-for-any-input fallback (never taken for this workload;
            // idempotent with the list path).
            for (int s = wid; s < N_TOK; s += 8) {
                const int id = __ldg(&ids[s]);
                if ((id >> TILE_BITS) == tile)
                    out[(long)s * D_MODEL + d0 + lane] =
                        sstage[lane * PAD + (id & (TILE_C - 1))];
            }
        }

        #pragma unroll
        for (int p = 0; p < 16; p++) rcur[p] = rnext[p];
    }
}

extern "C" void kernel_launch(void* const* d_in, const int* in_sizes, int n_in,
                              void* d_out, int out_size) {
    const int* ids = nullptr;
    const float* W = nullptr;
    for (int i = 0; i < n_in; i++) {
        if (in_sizes[i] == N_TOK) ids = (const int*)d_in[i];
        else if (in_sizes[i] == D_MODEL * VOCAB) W = (const float*)d_in[i];
    }
    float* out = (float*)d_out;

    gather_tile_kernel<<<N_TILES, 256>>>(ids, W, out);
}

// round 10
// speedup vs baseline: 1.1245x; 1.1245x over previous
#include <cuda_runtime.h>
#include <cuda_bf16.h>
#include <cstdint>

// Embedding gather: out[token, :] = W[:, ids[token]], W row-major [D_MODEL, VOCAB].
// R10: TILE_C=128 (512B DRAM bursts, 393 blocks -> half the filter traffic)
// with 512 threads/block so per-thread ILP stays at the proven R8 shape
// (8 LDG.32 in flight) while occupancy recovers to ~48 warps/SM.

#define VOCAB     50257
#define D_MODEL   1024
#define N_TOK     (4 * 4096)

#define TILE_C    128
#define TILE_BITS 7
#define N_TILES   ((VOCAB + TILE_C - 1) / TILE_C)   // 393
#define TILE_D    32
#define N_CHUNK   (D_MODEL / TILE_D)                // 32
#define PAD       (TILE_C + 1)                      // 129 (odd): conflict-free
#define STAGE_ELEMS (TILE_D * PAD)                  // 4128 floats
#define CAP       1024                              // max tokens/tile ~45 here
#define NTHREADS  512

__global__ __launch_bounds__(NTHREADS, 3)
void gather_tile_kernel(const int* __restrict__ ids,
                        const float* __restrict__ W,
                        float* __restrict__ out) {
    const int tile = blockIdx.x;

    __shared__ float buf[2][STAGE_ELEMS];   // 33 KB
    __shared__ int   s_list[CAP];           // 4 KB
    __shared__ int   s_cnt;

    const int tid  = threadIdx.x;
    const int lane = tid & 31;
    const int wid  = tid >> 5;                 // 16 warps
    const int c0   = tile * TILE_C;

    // Load mapping: lc = column 0..127, lr = row-phase 0..3.
    // 8 passes of 4 rows cover the 32-row chunk; each warp's lanes are
    // contiguous columns -> every LDG/STS is a 128B contiguous op, and the
    // 4 warps sharing a row form a 512B contiguous DRAM burst.
    const int lc = tid & (TILE_C - 1);
    const int lr = tid >> TILE_BITS;
    // Clamp OOB columns of last tile (never distributed: no id >= VOCAB).
    const int gcol = min(c0 + lc, VOCAB - 1);
    const float* __restrict__ col_base = W + gcol;

    if (tid == 0) s_cnt = 0;

    float rcur[8], rnext[8];

    // Prologue: issue chunk-0 DRAM loads first; the id-filter runs in their
    // shadow.
    #pragma unroll
    for (int p = 0; p < 8; p++)
        rcur[p] = __ldg(col_base + (long)(p * 4 + lr) * VOCAB);

    __syncthreads();   // s_cnt = 0 visible

    // Filter: find tokens whose id falls in this tile. Order irrelevant.
    const int4* __restrict__ ids4 = (const int4*)ids;
    for (int i = tid; i < N_TOK / 4; i += NTHREADS) {
        const int4 v = ids4[i];
        const int base_tok = i * 4;
        #pragma unroll
        for (int k = 0; k < 4; k++) {
            const int id = (&v.x)[k];
            if ((id >> TILE_BITS) == tile) {
                const int pos = atomicAdd(&s_cnt, 1);
                if (pos < CAP)
                    s_list[pos] = ((id & (TILE_C - 1)) << 16) | (base_tok + k);
            }
        }
    }
    __syncthreads();

    const int cnt = s_cnt;
    if (cnt == 0) return;                      // uniform: whole block exits
    const bool overflow = (cnt > CAP);
    const int n = overflow ? 0 : cnt;          // fast-path count

    for (int c = 0; c < N_CHUNK; c++) {
        // Issue chunk c+1 loads early (consumed next iteration).
        if (c + 1 < N_CHUNK) {
            #pragma unroll
            for (int p = 0; p < 8; p++)
                rnext[p] = __ldg(col_base + (long)((c + 1) * TILE_D + p * 4 + lr) * VOCAB);
        }

        // Stage chunk c to smem. Safe: buf[c&1] last distributed in iter c-2;
        // every warp passed iter c-1's barrier before this STS.
        float* sstage = &buf[c & 1][0];
        #pragma unroll
        for (int p = 0; p < 8; p++)
            sstage[(p * 4 + lr) * PAD + lc] = rcur[p];
        __syncthreads();

        // Distribute chunk c: row = lane -> one coalesced 128B store/token.
        const int d0 = c * TILE_D;
        for (int s = wid; s < n; s += 16) {
            const int pk    = s_list[s];
            const int col   = pk >> 16;
            const int token = pk & 0xFFFF;
            out[(long)token * D_MODEL + d0 + lane] = sstage[lane * PAD + col];
        }
        if (overflow) {
            // Correct-for-any-input fallback (never taken for this workload;
            // idempotent with the list path).
            for (int s = wid; s < N_TOK; s += 16) {
                const int id = __ldg(&ids[s]);
                if ((id >> TILE_BITS) == tile)
                    out[(long)s * D_MODEL + d0 + lane] =
                        sstage[lane * PAD + (id & (TILE_C - 1))];
            }
        }

        #pragma unroll
        for (int p = 0; p < 8; p++) rcur[p] = rnext[p];
    }
}

extern "C" void kernel_launch(void* const* d_in, const int* in_sizes, int n_in,
                              void* d_out, int out_size) {
    const int* ids = nullptr;
    const float* W = nullptr;
    for (int i = 0; i < n_in; i++) {
        if (in_sizes[i] == N_TOK) ids = (const int*)d_in[i];
        else if (in_sizes[i] == D_MODEL * VOCAB) W = (const float*)d_in[i];
    }
    float* out = (float*)d_out;

    gather_tile_kernel<<<N_TILES, NTHREADS>>>(ids, W, out);
}